// round 1
// baseline (speedup 1.0000x reference)
#include <cuda_runtime.h>
#include <cuda_bf16.h>

#define NN 50000
#define EE 800000
#define ETOT (EE + NN)
#define GG 128
#define NEG_SLOPE 0.2f

// ---------------- scratch (static device allocations) ----------------
__device__ float g_x1[NN * 16];
__device__ float g_x2[NN * 32];
__device__ float g_x3[NN * 128];
__device__ float g_x4[NN * 256];
__device__ float g_h [NN * 256];
__device__ float g_asrc[NN * 8];
__device__ float g_adst[NN * 8];
__device__ float g_m[NN * 8];
__device__ float g_s[NN * 8];
__device__ float g_dinv[NN];
__device__ int   g_counts[NN];     // degree counts, then reused as fill cursor
__device__ int   g_rowptr[NN + 1];
__device__ int   g_csr_src[ETOT];
__device__ float g_pool[GG * 432 + GG];   // [GG][432] sums + [GG] counts

// ---------------- CSR build ----------------
__global__ void count_edges_kernel(const int* __restrict__ ei, int* __restrict__ counts) {
    int e = blockIdx.x * blockDim.x + threadIdx.x;
    if (e >= ETOT) return;
    int dst = (e < EE) ? ei[EE + e] : (e - EE);
    atomicAdd(&counts[dst], 1);
}

__global__ void scan_kernel(const int* __restrict__ counts, int* __restrict__ rowptr) {
    __shared__ int wsum[32];
    __shared__ int carry_sh;
    int tid = threadIdx.x, lane = tid & 31, wid = tid >> 5;
    if (tid == 0) { carry_sh = 0; rowptr[0] = 0; }
    __syncthreads();
    for (int base = 0; base < NN; base += 1024) {
        int i = base + tid;
        int v = (i < NN) ? counts[i] : 0;
#pragma unroll
        for (int o = 1; o < 32; o <<= 1) {
            int t = __shfl_up_sync(0xffffffffu, v, o);
            if (lane >= o) v += t;
        }
        if (lane == 31) wsum[wid] = v;
        __syncthreads();
        if (wid == 0) {
            int w = wsum[lane];
#pragma unroll
            for (int o = 1; o < 32; o <<= 1) {
                int t = __shfl_up_sync(0xffffffffu, w, o);
                if (lane >= o) w += t;
            }
            wsum[lane] = w;
        }
        __syncthreads();
        int off = (wid > 0) ? wsum[wid - 1] : 0;
        int carry = carry_sh;
        if (i < NN) rowptr[i + 1] = v + off + carry;
        int total = wsum[31];
        __syncthreads();
        if (tid == 0) carry_sh = carry + total;
        __syncthreads();
    }
}

__global__ void prep_kernel(int* __restrict__ counts, const int* __restrict__ rowptr,
                            float* __restrict__ dinv) {
    int n = blockIdx.x * blockDim.x + threadIdx.x;
    if (n >= NN) return;
    int d = counts[n];
    dinv[n] = rsqrtf((float)(d > 0 ? d : 1));
    counts[n] = rowptr[n];   // becomes fill cursor
}

__global__ void fill_csr_kernel(const int* __restrict__ ei, int* __restrict__ cursor,
                                int* __restrict__ csr) {
    int e = blockIdx.x * blockDim.x + threadIdx.x;
    if (e >= ETOT) return;
    int src, dst;
    if (e < EE) { src = ei[e]; dst = ei[EE + e]; }
    else        { src = dst = e - EE; }
    int pos = atomicAdd(&cursor[dst], 1);
    csr[pos] = src;
}

// ---------------- GEMM: Y[N,M] = X[N,K] @ W[K,M] ----------------
template<int K, int M>
__global__ void gemm_kernel(const float* __restrict__ X, const float* __restrict__ W,
                            float* __restrict__ Y) {
    constexpr int CT = (M < 64) ? M : 64;
    constexpr int KC = (K < 64) ? K : 64;
    constexpr int TX = CT / 4;
    constexpr int NT = TX * 16;
    constexpr int RP = 68;                 // padded pitch for Xs rows
    __shared__ float Xs[KC * RP];
    __shared__ float Ws[KC * CT];
    int row0 = blockIdx.x * 64;
    int c0 = blockIdx.y * CT;
    int tid = threadIdx.y * TX + threadIdx.x;
    float acc[4][4] = {};
    for (int k0 = 0; k0 < K; k0 += KC) {
        for (int idx = tid; idx < 64 * KC; idx += NT) {
            int r = idx / KC, k = idx % KC;
            int gr = row0 + r;
            Xs[k * RP + r] = (gr < NN) ? X[gr * K + k0 + k] : 0.f;
        }
        for (int idx = tid; idx < KC * CT; idx += NT) {
            int k = idx / CT, c = idx % CT;
            Ws[k * CT + c] = W[(k0 + k) * M + c0 + c];
        }
        __syncthreads();
#pragma unroll 8
        for (int k = 0; k < KC; k++) {
            float4 xv = *(const float4*)&Xs[k * RP + 4 * threadIdx.y];
            float4 wv = *(const float4*)&Ws[k * CT + 4 * threadIdx.x];
            float xa[4] = {xv.x, xv.y, xv.z, xv.w};
            float wa[4] = {wv.x, wv.y, wv.z, wv.w};
#pragma unroll
            for (int i = 0; i < 4; i++)
#pragma unroll
                for (int j = 0; j < 4; j++)
                    acc[i][j] += xa[i] * wa[j];
        }
        __syncthreads();
    }
#pragma unroll
    for (int i = 0; i < 4; i++) {
        int r = row0 + 4 * threadIdx.y + i;
        if (r < NN) {
            float4 o = make_float4(acc[i][0], acc[i][1], acc[i][2], acc[i][3]);
            *(float4*)&Y[r * M + c0 + 4 * threadIdx.x] = o;
        }
    }
}

template<int K, int M>
static void launch_gemm(const float* X, const float* W, float* Y) {
    constexpr int CT = (M < 64) ? M : 64;
    dim3 b(CT / 4, 16), g((NN + 63) / 64, M / CT);
    gemm_kernel<K, M><<<g, b>>>(X, W, Y);
}

// ---------------- GCN aggregate: out = relu(dinv[n]*sum(h[s]*dinv[s]) + b) ----------------
template<int C>
__global__ void gcn_agg_kernel(const float* __restrict__ h, const float* __restrict__ dinv,
                               const int* __restrict__ rowptr, const int* __restrict__ csr,
                               const float* __restrict__ bias, float* __restrict__ out) {
    constexpr int NP = 32 / C;
    int warp = (blockIdx.x * blockDim.x + threadIdx.x) >> 5;
    int lane = threadIdx.x & 31;
    int sub = lane / C, c = lane % C;
    int n = warp * NP + sub;
    if (n >= NN) return;
    int r0 = rowptr[n], r1 = rowptr[n + 1];
    float acc = 0.f;
    for (int j = r0; j < r1; j++) {
        int s = csr[j];
        acc += h[s * C + c] * dinv[s];
    }
    float v = acc * dinv[n] + bias[c];
    out[n * C + c] = fmaxf(v, 0.f);
}

// ---------------- GAT: attention coefficients per node ----------------
template<int H>
__global__ void att_coef_kernel(const float* __restrict__ h, const float* __restrict__ att_s,
                                const float* __restrict__ att_d,
                                float* __restrict__ asrc, float* __restrict__ adst) {
    int warp = (blockIdx.x * blockDim.x + threadIdx.x) >> 5;
    int lane = threadIdx.x & 31;
    int n = warp;
    if (n >= NN) return;
#pragma unroll
    for (int hd = 0; hd < H; hd++) {
        float v = h[n * H * 32 + hd * 32 + lane];
        float vs = v * att_s[hd * 32 + lane];
        float vd = v * att_d[hd * 32 + lane];
#pragma unroll
        for (int o = 16; o; o >>= 1) {
            vs += __shfl_xor_sync(0xffffffffu, vs, o);
            vd += __shfl_xor_sync(0xffffffffu, vd, o);
        }
        if (lane == 0) { asrc[n * H + hd] = vs; adst[n * H + hd] = vd; }
    }
}

// ---------------- GAT: segment max + sum(exp) per dst node ----------------
template<int H>
__global__ void gat_maxsum_kernel(const float* __restrict__ asrc, const float* __restrict__ adst,
                                  const int* __restrict__ rowptr, const int* __restrict__ csr,
                                  float* __restrict__ mArr, float* __restrict__ sArr) {
    int warp = (blockIdx.x * blockDim.x + threadIdx.x) >> 5;
    int lane = threadIdx.x & 31;
    int n = warp;
    if (n >= NN) return;
    float ad[H];
#pragma unroll
    for (int hd = 0; hd < H; hd++) ad[hd] = adst[n * H + hd];
    int r0 = rowptr[n], r1 = rowptr[n + 1];
    float mx[H];
#pragma unroll
    for (int hd = 0; hd < H; hd++) mx[hd] = -1e30f;
    for (int j = r0 + lane; j < r1; j += 32) {
        int s = csr[j];
#pragma unroll
        for (int hd = 0; hd < H; hd++) {
            float e = asrc[s * H + hd] + ad[hd];
            e = e > 0.f ? e : NEG_SLOPE * e;
            mx[hd] = fmaxf(mx[hd], e);
        }
    }
#pragma unroll
    for (int hd = 0; hd < H; hd++)
#pragma unroll
        for (int o = 16; o; o >>= 1) mx[hd] = fmaxf(mx[hd], __shfl_xor_sync(0xffffffffu, mx[hd], o));
    float sm[H];
#pragma unroll
    for (int hd = 0; hd < H; hd++) sm[hd] = 0.f;
    for (int j = r0 + lane; j < r1; j += 32) {
        int s = csr[j];
#pragma unroll
        for (int hd = 0; hd < H; hd++) {
            float e = asrc[s * H + hd] + ad[hd];
            e = e > 0.f ? e : NEG_SLOPE * e;
            sm[hd] += __expf(e - mx[hd]);
        }
    }
#pragma unroll
    for (int hd = 0; hd < H; hd++)
#pragma unroll
        for (int o = 16; o; o >>= 1) sm[hd] += __shfl_xor_sync(0xffffffffu, sm[hd], o);
    if (lane == 0)
#pragma unroll
        for (int hd = 0; hd < H; hd++) { mArr[n * H + hd] = mx[hd]; sArr[n * H + hd] = sm[hd]; }
}

// ---------------- GAT: weighted aggregation ----------------
template<int H>
__global__ void gat_agg_kernel(const float* __restrict__ h, const float* __restrict__ asrc,
                               const float* __restrict__ adst, const float* __restrict__ mArr,
                               const float* __restrict__ sArr, const int* __restrict__ rowptr,
                               const int* __restrict__ csr, const float* __restrict__ bias,
                               float* __restrict__ out) {
    constexpr int HC = H * 32;
    constexpr int CPT = HC / 128;
    int n = blockIdx.x, t = threadIdx.x;
    int cb = t * CPT, hd = cb >> 5;
    float ad = adst[n * H + hd];
    float mm = mArr[n * H + hd];
    float invs = 1.f / sArr[n * H + hd];
    float acc0 = 0.f, acc1 = 0.f;
    int r0 = rowptr[n], r1 = rowptr[n + 1];
    for (int j = r0; j < r1; j++) {
        int s = csr[j];
        float e = asrc[s * H + hd] + ad;
        e = e > 0.f ? e : NEG_SLOPE * e;
        float alpha = __expf(e - mm) * invs;
        if constexpr (CPT == 2) {
            float2 hv = *(const float2*)&h[s * HC + cb];
            acc0 += hv.x * alpha;
            acc1 += hv.y * alpha;
        } else {
            acc0 += h[s * HC + cb] * alpha;
        }
    }
    out[n * HC + cb] = fmaxf(acc0 + bias[cb], 0.f);
    if constexpr (CPT == 2)
        out[n * HC + cb + 1] = fmaxf(acc1 + bias[cb + 1], 0.f);
}

// ---------------- pooling (atomic) ----------------
__global__ void pool_kernel(const float* __restrict__ x1, const float* __restrict__ x2,
                            const float* __restrict__ x3, const float* __restrict__ x4,
                            const int* __restrict__ batch, float* __restrict__ pool) {
    int n = blockIdx.x, t = threadIdx.x;
    int b = batch[n];
    if (t == 0) atomicAdd(&pool[GG * 432 + b], 1.f);
    for (int c = t; c < 432; c += 128) {
        float v;
        if (c < 16)       v = x1[n * 16 + c];
        else if (c < 48)  v = x2[n * 32 + (c - 16)];
        else if (c < 176) v = x3[n * 128 + (c - 48)];
        else              v = x4[n * 256 + (c - 176)];
        atomicAdd(&pool[b * 432 + c], v);
    }
}

// ---------------- final MLP ----------------
__global__ void fc_kernel(const float* __restrict__ pool,
                          const float* __restrict__ W1, const float* __restrict__ b1,
                          const float* __restrict__ W2, const float* __restrict__ b2,
                          float* __restrict__ out) {
    int g = blockIdx.x, t = threadIdx.x;   // 128 threads
    __shared__ float xp[432];
    __shared__ float ws[4];
    float invc = 1.f / fmaxf(pool[GG * 432 + g], 1.f);
    for (int i = t; i < 432; i += 128) xp[i] = pool[g * 432 + i] * invc;
    __syncthreads();
    float acc = b1[t];
    for (int i = 0; i < 432; i++) acc += xp[i] * W1[i * 128 + t];
    acc = fmaxf(acc, 0.f);
    float v = acc * W2[t];
#pragma unroll
    for (int o = 16; o; o >>= 1) v += __shfl_xor_sync(0xffffffffu, v, o);
    if ((t & 31) == 0) ws[t >> 5] = v;
    __syncthreads();
    if (t == 0) out[g] = ws[0] + ws[1] + ws[2] + ws[3] + b2[0];
}

// ---------------- launch ----------------
extern "C" void kernel_launch(void* const* d_in, const int* in_sizes, int n_in,
                              void* d_out, int out_size) {
    const float* x    = (const float*)d_in[0];
    const int*   ei   = (const int*)d_in[1];
    const int*   batch= (const int*)d_in[2];
    const float* W1   = (const float*)d_in[3];
    const float* b1   = (const float*)d_in[4];
    const float* W2   = (const float*)d_in[5];
    const float* b2   = (const float*)d_in[6];
    const float* W3   = (const float*)d_in[7];
    const float* as3  = (const float*)d_in[8];
    const float* ad3  = (const float*)d_in[9];
    const float* b3   = (const float*)d_in[10];
    const float* W4   = (const float*)d_in[11];
    const float* as4  = (const float*)d_in[12];
    const float* ad4  = (const float*)d_in[13];
    const float* b4   = (const float*)d_in[14];
    const float* Wfc1 = (const float*)d_in[15];
    const float* bfc1 = (const float*)d_in[16];
    const float* Wfc2 = (const float*)d_in[17];
    const float* bfc2 = (const float*)d_in[18];
    float* out = (float*)d_out;

    // resolve device symbol addresses (host-side, not captured; done every call, cheap)
    static float *p_x1=nullptr,*p_x2,*p_x3,*p_x4,*p_h,*p_asrc,*p_adst,*p_m,*p_s,*p_dinv,*p_pool;
    static int *p_counts,*p_rowptr,*p_csr;
    if (!p_x1) {
        cudaGetSymbolAddress((void**)&p_x1, g_x1);
        cudaGetSymbolAddress((void**)&p_x2, g_x2);
        cudaGetSymbolAddress((void**)&p_x3, g_x3);
        cudaGetSymbolAddress((void**)&p_x4, g_x4);
        cudaGetSymbolAddress((void**)&p_h, g_h);
        cudaGetSymbolAddress((void**)&p_asrc, g_asrc);
        cudaGetSymbolAddress((void**)&p_adst, g_adst);
        cudaGetSymbolAddress((void**)&p_m, g_m);
        cudaGetSymbolAddress((void**)&p_s, g_s);
        cudaGetSymbolAddress((void**)&p_dinv, g_dinv);
        cudaGetSymbolAddress((void**)&p_pool, g_pool);
        cudaGetSymbolAddress((void**)&p_counts, g_counts);
        cudaGetSymbolAddress((void**)&p_rowptr, g_rowptr);
        cudaGetSymbolAddress((void**)&p_csr, g_csr_src);
    }

    // 1. CSR build
    cudaMemsetAsync(p_counts, 0, NN * sizeof(int));
    count_edges_kernel<<<(ETOT + 255) / 256, 256>>>(ei, p_counts);
    scan_kernel<<<1, 1024>>>(p_counts, p_rowptr);
    prep_kernel<<<(NN + 255) / 256, 256>>>(p_counts, p_rowptr, p_dinv);
    fill_csr_kernel<<<(ETOT + 255) / 256, 256>>>(ei, p_counts, p_csr);

    // 2. GCN layer 1 (128 -> 16)
    launch_gemm<128, 16>(x, W1, p_h);
    gcn_agg_kernel<16><<<(NN / 2 * 32 + 255) / 256, 256>>>(p_h, p_dinv, p_rowptr, p_csr, b1, p_x1);

    // 3. GCN layer 2 (16 -> 32)
    launch_gemm<16, 32>(p_x1, W2, p_h);
    gcn_agg_kernel<32><<<(NN * 32 + 255) / 256, 256>>>(p_h, p_dinv, p_rowptr, p_csr, b2, p_x2);

    // 4. GAT layer 3 (32 -> 4x32)
    launch_gemm<32, 128>(p_x2, W3, p_h);
    att_coef_kernel<4><<<(NN * 32 + 255) / 256, 256>>>(p_h, as3, ad3, p_asrc, p_adst);
    gat_maxsum_kernel<4><<<(NN * 32 + 255) / 256, 256>>>(p_asrc, p_adst, p_rowptr, p_csr, p_m, p_s);
    gat_agg_kernel<4><<<NN, 128>>>(p_h, p_asrc, p_adst, p_m, p_s, p_rowptr, p_csr, b3, p_x3);

    // 5. GAT layer 4 (128 -> 8x32)
    launch_gemm<128, 256>(p_x3, W4, p_h);
    att_coef_kernel<8><<<(NN * 32 + 255) / 256, 256>>>(p_h, as4, ad4, p_asrc, p_adst);
    gat_maxsum_kernel<8><<<(NN * 32 + 255) / 256, 256>>>(p_asrc, p_adst, p_rowptr, p_csr, p_m, p_s);
    gat_agg_kernel<8><<<NN, 128>>>(p_h, p_asrc, p_adst, p_m, p_s, p_rowptr, p_csr, b4, p_x4);

    // 6. global mean pool + MLP
    cudaMemsetAsync(p_pool, 0, (GG * 432 + GG) * sizeof(float));
    pool_kernel<<<NN, 128>>>(p_x1, p_x2, p_x3, p_x4, batch, p_pool);
    fc_kernel<<<GG, 128>>>(p_pool, Wfc1, bfc1, Wfc2, bfc2, out);
}

// round 2
// speedup vs baseline: 1.3014x; 1.3014x over previous
#include <cuda_runtime.h>

#define NN 50000
#define EE 800000
#define ETOT (EE + NN)
#define GG 128
#define NEG_SLOPE 0.2f

typedef unsigned long long ull;
typedef unsigned int uint;

union F4U { float4 f; ull u[2]; };
union F2U { float2 f; ull u; };

__device__ __forceinline__ ull fma2(ull a, ull b, ull c) {
    ull d; asm("fma.rn.f32x2 %0,%1,%2,%3;" : "=l"(d) : "l"(a), "l"(b), "l"(c)); return d;
}
__device__ __forceinline__ ull add2(ull a, ull b) {
    ull d; asm("add.rn.f32x2 %0,%1,%2;" : "=l"(d) : "l"(a), "l"(b)); return d;
}
__device__ __forceinline__ ull pack2(float x) {
    F2U t; t.f = make_float2(x, x); return t.u;
}
__device__ __forceinline__ float2 unpack2(ull v) { F2U t; t.u = v; return t.f; }

// ---------------- scratch ----------------
__device__ float g_x1[NN * 16];
__device__ float g_x2[NN * 32];
__device__ float g_x3[NN * 128];
__device__ float g_x4[NN * 256];
__device__ float g_h [NN * 256];
__device__ float g_asrc[NN * 8];
__device__ float g_adst[NN * 8];
__device__ float g_m[NN * 8];
__device__ float g_s[NN * 8];
__device__ float g_ex[(size_t)ETOT * 8];
__device__ float g_dinv[NN];
__device__ int   g_counts[NN];
__device__ int   g_rowptr[NN + 1];
__device__ int   g_csr_src[ETOT];
__device__ int   g_gstart[GG + 1];
__device__ float g_pool[GG * 432];

// ---------------- CSR build ----------------
__global__ void count_edges_kernel(const int* __restrict__ ei, int* __restrict__ counts) {
    int e = blockIdx.x * blockDim.x + threadIdx.x;
    if (e >= ETOT) return;
    int dst = (e < EE) ? ei[EE + e] : (e - EE);
    atomicAdd(&counts[dst], 1);
}

__global__ void scan_kernel(const int* __restrict__ counts, int* __restrict__ rowptr) {
    __shared__ int wsum[32];
    __shared__ int carry_sh;
    int tid = threadIdx.x, lane = tid & 31, wid = tid >> 5;
    if (tid == 0) { carry_sh = 0; rowptr[0] = 0; }
    __syncthreads();
    for (int base = 0; base < NN; base += 1024) {
        int i = base + tid;
        int v = (i < NN) ? counts[i] : 0;
#pragma unroll
        for (int o = 1; o < 32; o <<= 1) {
            int t = __shfl_up_sync(0xffffffffu, v, o);
            if (lane >= o) v += t;
        }
        if (lane == 31) wsum[wid] = v;
        __syncthreads();
        if (wid == 0) {
            int w = wsum[lane];
#pragma unroll
            for (int o = 1; o < 32; o <<= 1) {
                int t = __shfl_up_sync(0xffffffffu, w, o);
                if (lane >= o) w += t;
            }
            wsum[lane] = w;
        }
        __syncthreads();
        int off = (wid > 0) ? wsum[wid - 1] : 0;
        int carry = carry_sh;
        if (i < NN) rowptr[i + 1] = v + off + carry;
        int total = wsum[31];
        __syncthreads();
        if (tid == 0) carry_sh = carry + total;
        __syncthreads();
    }
}

__global__ void prep_kernel(int* __restrict__ counts, const int* __restrict__ rowptr,
                            float* __restrict__ dinv) {
    int n = blockIdx.x * blockDim.x + threadIdx.x;
    if (n >= NN) return;
    int d = counts[n];
    dinv[n] = rsqrtf((float)(d > 0 ? d : 1));
    counts[n] = rowptr[n];
}

__global__ void fill_csr_kernel(const int* __restrict__ ei, int* __restrict__ cursor,
                                int* __restrict__ csr) {
    int e = blockIdx.x * blockDim.x + threadIdx.x;
    if (e >= ETOT) return;
    int src, dst;
    if (e < EE) { src = ei[e]; dst = ei[EE + e]; }
    else        { src = dst = e - EE; }
    int pos = atomicAdd(&cursor[dst], 1);
    csr[pos] = src;
}

// graph start offsets from sorted batch
__global__ void gstart_kernel(const int* __restrict__ batch, int* __restrict__ gstart) {
    int n = blockIdx.x * blockDim.x + threadIdx.x;
    if (n >= NN) return;
    int b = batch[n];
    if (n == 0) { for (int g = 0; g <= b; g++) gstart[g] = 0; }
    else {
        int pb = batch[n - 1];
        for (int g = pb + 1; g <= b; g++) gstart[g] = n;
    }
    if (n == NN - 1) { for (int g = b + 1; g <= GG; g++) gstart[g] = NN; }
}

// ---------------- small GEMM (M=16/32): Y[N,M] = X[N,K] @ W[K,M] ----------------
template<int K, int M>
__global__ void gemm_small_kernel(const float* __restrict__ X, const float* __restrict__ W,
                                  float* __restrict__ Y) {
    constexpr int CT = M;
    constexpr int KC = (K < 64) ? K : 64;
    constexpr int TX = CT / 4;
    constexpr int NT = TX * 16;
    constexpr int RP = 68;
    __shared__ float Xs[KC * RP];
    __shared__ float Ws[KC * CT];
    int row0 = blockIdx.x * 64;
    int tid = threadIdx.y * TX + threadIdx.x;
    float acc[4][4] = {};
    for (int k0 = 0; k0 < K; k0 += KC) {
        for (int idx = tid; idx < 64 * KC; idx += NT) {
            int r = idx / KC, k = idx % KC;
            int gr = row0 + r;
            Xs[k * RP + r] = (gr < NN) ? X[gr * K + k0 + k] : 0.f;
        }
        for (int idx = tid; idx < KC * CT; idx += NT) {
            int k = idx / CT, c = idx % CT;
            Ws[k * CT + c] = W[(k0 + k) * M + c];
        }
        __syncthreads();
#pragma unroll 8
        for (int k = 0; k < KC; k++) {
            float4 xv = *(const float4*)&Xs[k * RP + 4 * threadIdx.y];
            float4 wv = *(const float4*)&Ws[k * CT + 4 * threadIdx.x];
            float xa[4] = {xv.x, xv.y, xv.z, xv.w};
            float wa[4] = {wv.x, wv.y, wv.z, wv.w};
#pragma unroll
            for (int i = 0; i < 4; i++)
#pragma unroll
                for (int j = 0; j < 4; j++)
                    acc[i][j] += xa[i] * wa[j];
        }
        __syncthreads();
    }
#pragma unroll
    for (int i = 0; i < 4; i++) {
        int r = row0 + 4 * threadIdx.y + i;
        if (r < NN) {
            float4 o = make_float4(acc[i][0], acc[i][1], acc[i][2], acc[i][3]);
            *(float4*)&Y[r * M + 4 * threadIdx.x] = o;
        }
    }
}

// ---------------- big GEMM (M>=128): 128x64 tile, 8x8 micro-tile, f32x2 ----------------
template<int K, int M>
__global__ __launch_bounds__(128) void gemm_big_kernel(const float* __restrict__ X,
                                                       const float* __restrict__ W,
                                                       float* __restrict__ Y) {
    constexpr int KC = (K < 32) ? K : 32;
    constexpr int RP = 132;
    __shared__ float Xs[KC * RP];
    __shared__ float Ws[KC * 64];
    int tx = threadIdx.x, ty = threadIdx.y;      // (8,16)
    int tid = ty * 8 + tx;
    int row0 = blockIdx.x * 128;
    int c0 = blockIdx.y * 64;
    ull acc[4][8];
#pragma unroll
    for (int p = 0; p < 4; p++)
#pragma unroll
        for (int j = 0; j < 8; j++) acc[p][j] = 0ull;

    for (int k0 = 0; k0 < K; k0 += KC) {
        // load X tile (128 rows x KC), float4 global reads
        for (int idx = tid; idx < 128 * (KC / 4); idx += 128) {
            int r = idx / (KC / 4);
            int k4 = (idx % (KC / 4)) * 4;
            int gr = row0 + r;
            float4 v = make_float4(0.f, 0.f, 0.f, 0.f);
            if (gr < NN) v = *(const float4*)&X[gr * K + k0 + k4];
            Xs[(k4 + 0) * RP + r] = v.x;
            Xs[(k4 + 1) * RP + r] = v.y;
            Xs[(k4 + 2) * RP + r] = v.z;
            Xs[(k4 + 3) * RP + r] = v.w;
        }
        // load W tile (KC x 64)
        for (int idx = tid; idx < KC * 16; idx += 128) {
            int k = idx / 16;
            int c4 = (idx % 16) * 4;
            *(float4*)&Ws[k * 64 + c4] = *(const float4*)&W[(k0 + k) * M + c0 + c4];
        }
        __syncthreads();
#pragma unroll 8
        for (int k = 0; k < KC; k++) {
            const float* xr = &Xs[k * RP + 8 * ty];
            F4U xa, xb;
            xa.f = *(const float4*)xr;
            xb.f = *(const float4*)(xr + 4);
            ull x2[4] = {xa.u[0], xa.u[1], xb.u[0], xb.u[1]};
            const float* wr = &Ws[k * 64 + 8 * tx];
            float4 wa = *(const float4*)wr;
            float4 wb = *(const float4*)(wr + 4);
            ull w2[8];
            w2[0] = pack2(wa.x); w2[1] = pack2(wa.y); w2[2] = pack2(wa.z); w2[3] = pack2(wa.w);
            w2[4] = pack2(wb.x); w2[5] = pack2(wb.y); w2[6] = pack2(wb.z); w2[7] = pack2(wb.w);
#pragma unroll
            for (int p = 0; p < 4; p++)
#pragma unroll
                for (int j = 0; j < 8; j++)
                    acc[p][j] = fma2(x2[p], w2[j], acc[p][j]);
        }
        __syncthreads();
    }
    // store: acc[p][j] = { out[8ty+2p][c0+8tx+j], out[8ty+2p+1][...] }
#pragma unroll
    for (int p = 0; p < 4; p++) {
        float rlo[8], rhi[8];
#pragma unroll
        for (int j = 0; j < 8; j++) {
            float2 t = unpack2(acc[p][j]);
            rlo[j] = t.x; rhi[j] = t.y;
        }
        int r = row0 + 8 * ty + 2 * p;
        if (r < NN) {
            *(float4*)&Y[r * M + c0 + 8 * tx]     = make_float4(rlo[0], rlo[1], rlo[2], rlo[3]);
            *(float4*)&Y[r * M + c0 + 8 * tx + 4] = make_float4(rlo[4], rlo[5], rlo[6], rlo[7]);
        }
        if (r + 1 < NN) {
            *(float4*)&Y[(r + 1) * M + c0 + 8 * tx]     = make_float4(rhi[0], rhi[1], rhi[2], rhi[3]);
            *(float4*)&Y[(r + 1) * M + c0 + 8 * tx + 4] = make_float4(rhi[4], rhi[5], rhi[6], rhi[7]);
        }
    }
}

// ---------------- GCN aggregate: 4 channels/thread, f32x2 ----------------
template<int C>
__global__ void gcn_agg_kernel(const float* __restrict__ h, const float* __restrict__ dinv,
                               const int* __restrict__ rowptr, const int* __restrict__ csr,
                               const float* __restrict__ bias, float* __restrict__ out) {
    constexpr int TPN = C / 4;
    int gtid = blockIdx.x * blockDim.x + threadIdx.x;
    int n = gtid / TPN;
    int ch = 4 * (gtid % TPN);
    if (n >= NN) return;
    int r0 = rowptr[n], r1 = rowptr[n + 1];
    const float* hb = h + ch;
    ull a0 = 0ull, a1 = 0ull;
    for (int j = r0; j < r1; j++) {
        int s = csr[j];
        ull dv2 = pack2(dinv[s]);
        F4U hv; hv.f = *(const float4*)(hb + s * C);
        a0 = fma2(hv.u[0], dv2, a0);
        a1 = fma2(hv.u[1], dv2, a1);
    }
    float dn = dinv[n];
    float2 r01 = unpack2(a0), r23 = unpack2(a1);
    float4 b = *(const float4*)&bias[ch];
    float4 o;
    o.x = fmaxf(r01.x * dn + b.x, 0.f);
    o.y = fmaxf(r01.y * dn + b.y, 0.f);
    o.z = fmaxf(r23.x * dn + b.z, 0.f);
    o.w = fmaxf(r23.y * dn + b.w, 0.f);
    *(float4*)&out[n * C + ch] = o;
}

// ---------------- GAT: attention coefficients per node ----------------
template<int H>
__global__ void att_coef_kernel(const float* __restrict__ h, const float* __restrict__ att_s,
                                const float* __restrict__ att_d,
                                float* __restrict__ asrc, float* __restrict__ adst) {
    int warp = (blockIdx.x * blockDim.x + threadIdx.x) >> 5;
    int lane = threadIdx.x & 31;
    int n = warp;
    if (n >= NN) return;
#pragma unroll
    for (int hd = 0; hd < H; hd++) {
        float v = h[n * H * 32 + hd * 32 + lane];
        float vs = v * att_s[hd * 32 + lane];
        float vd = v * att_d[hd * 32 + lane];
#pragma unroll
        for (int o = 16; o; o >>= 1) {
            vs += __shfl_xor_sync(0xffffffffu, vs, o);
            vd += __shfl_xor_sync(0xffffffffu, vd, o);
        }
        if (lane == 0) { asrc[n * H + hd] = vs; adst[n * H + hd] = vd; }
    }
}

// ---------------- GAT: max + sum(exp), cache exp(e-m) per (edge,head) ----------------
template<int H>
__global__ void gat_maxsum_kernel(const float* __restrict__ asrc, const float* __restrict__ adst,
                                  const int* __restrict__ rowptr, const int* __restrict__ csr,
                                  float* __restrict__ mArr, float* __restrict__ sArr,
                                  float* __restrict__ ex) {
    int warp = (blockIdx.x * blockDim.x + threadIdx.x) >> 5;
    int lane = threadIdx.x & 31;
    int n = warp;
    if (n >= NN) return;
    float ad[H];
#pragma unroll
    for (int q = 0; q < H / 4; q++) {
        float4 v = *(const float4*)&adst[n * H + 4 * q];
        ad[4 * q + 0] = v.x; ad[4 * q + 1] = v.y; ad[4 * q + 2] = v.z; ad[4 * q + 3] = v.w;
    }
    int r0 = rowptr[n], r1 = rowptr[n + 1];
    float mx[H];
#pragma unroll
    for (int hd = 0; hd < H; hd++) mx[hd] = -1e30f;
    for (int j = r0 + lane; j < r1; j += 32) {
        int s = csr[j];
        float as[H];
#pragma unroll
        for (int q = 0; q < H / 4; q++) {
            float4 v = *(const float4*)&asrc[s * H + 4 * q];
            as[4 * q + 0] = v.x; as[4 * q + 1] = v.y; as[4 * q + 2] = v.z; as[4 * q + 3] = v.w;
        }
#pragma unroll
        for (int hd = 0; hd < H; hd++) {
            float e = as[hd] + ad[hd];
            e = fmaxf(e, NEG_SLOPE * e);
            mx[hd] = fmaxf(mx[hd], e);
        }
    }
#pragma unroll
    for (int hd = 0; hd < H; hd++)
#pragma unroll
        for (int o = 16; o; o >>= 1) mx[hd] = fmaxf(mx[hd], __shfl_xor_sync(0xffffffffu, mx[hd], o));
    float sm[H];
#pragma unroll
    for (int hd = 0; hd < H; hd++) sm[hd] = 0.f;
    for (int j = r0 + lane; j < r1; j += 32) {
        int s = csr[j];
        float as[H];
#pragma unroll
        for (int q = 0; q < H / 4; q++) {
            float4 v = *(const float4*)&asrc[s * H + 4 * q];
            as[4 * q + 0] = v.x; as[4 * q + 1] = v.y; as[4 * q + 2] = v.z; as[4 * q + 3] = v.w;
        }
        float exv[H];
#pragma unroll
        for (int hd = 0; hd < H; hd++) {
            float e = as[hd] + ad[hd];
            e = fmaxf(e, NEG_SLOPE * e);
            float xv = __expf(e - mx[hd]);
            exv[hd] = xv;
            sm[hd] += xv;
        }
#pragma unroll
        for (int q = 0; q < H / 4; q++)
            *(float4*)&ex[(size_t)j * H + 4 * q] =
                make_float4(exv[4 * q + 0], exv[4 * q + 1], exv[4 * q + 2], exv[4 * q + 3]);
    }
#pragma unroll
    for (int hd = 0; hd < H; hd++)
#pragma unroll
        for (int o = 16; o; o >>= 1) sm[hd] += __shfl_xor_sync(0xffffffffu, sm[hd], o);
    if (lane == 0) {
#pragma unroll
        for (int hd = 0; hd < H; hd++) { mArr[n * H + hd] = mx[hd]; sArr[n * H + hd] = sm[hd]; }
    }
}

// ---------------- GAT aggregation: chunked two-phase, float4 + f32x2 ----------------
template<int H>
__global__ __launch_bounds__(128) void gat_agg_kernel(
        const float* __restrict__ h, const float* __restrict__ ex,
        const float* __restrict__ sArr, const int* __restrict__ rowptr,
        const int* __restrict__ csr, const float* __restrict__ bias,
        float* __restrict__ out) {
    constexpr int HC = H * 32;
    constexpr int TPN = HC / 4;      // 64 (H=8) / 32 (H=4)
    constexpr int NPB = 128 / TPN;   // 2 / 4
    constexpr int CH = 32;
    __shared__ float2 al_sh[NPB][CH * H];
    __shared__ int off_sh[NPB][CH];
    __shared__ float inv_sh[NPB][H];
    __shared__ int r0_sh[NPB];
    __shared__ int cnt_sh[NPB];
    __shared__ int mx_sh;

    int tid = threadIdx.x;
    int g = tid / TPN, tg = tid % TPN;
    int n = blockIdx.x * NPB + g;
    if (tid == 0) mx_sh = 0;
    if (tg < H) inv_sh[g][tg] = 1.f / sArr[n * H + tg];
    if (tg == 0) {
        int r0 = rowptr[n], r1 = rowptr[n + 1];
        r0_sh[g] = r0;
        cnt_sh[g] = r1 - r0;
    }
    __syncthreads();
    if (tg == 0) atomicMax(&mx_sh, cnt_sh[g]);
    __syncthreads();
    int cnt = cnt_sh[g], r0 = r0_sh[g];
    int nch = (mx_sh + CH - 1) / CH;
    int ch0 = 4 * tg;
    int hd = tg >> 3;                 // ch0/32 for both H=4 and H=8
    const float* hb = h + ch0;
    ull a0 = 0ull, a1 = 0ull;

    for (int c = 0; c < nch; c++) {
        int base = c * CH;
        int cc = min(CH, cnt - base);     // may be <= 0
        // Phase A: stage alpha (and src offsets) into shared
#pragma unroll
        for (int it = 0; it < CH * H / TPN; it++) {
            int task = tg + it * TPN;
            int e = task / H;
            int hh = task - e * H;
            if (e < cc) {
                int j = r0 + base + e;
                float a = ex[(size_t)j * H + hh] * inv_sh[g][hh];
                al_sh[g][task] = make_float2(a, a);
                if (hh == 0) off_sh[g][e] = csr[j] * HC;
            }
        }
        __syncthreads();
        // Phase B: accumulate
        int e = 0;
        for (; e + 4 <= cc; e += 4) {
            int o0 = off_sh[g][e], o1 = off_sh[g][e + 1], o2 = off_sh[g][e + 2], o3 = off_sh[g][e + 3];
            F2U A0, A1, A2, A3;
            A0.f = al_sh[g][(e + 0) * H + hd];
            A1.f = al_sh[g][(e + 1) * H + hd];
            A2.f = al_sh[g][(e + 2) * H + hd];
            A3.f = al_sh[g][(e + 3) * H + hd];
            F4U H0, H1, H2, H3;
            H0.f = *(const float4*)(hb + o0);
            H1.f = *(const float4*)(hb + o1);
            H2.f = *(const float4*)(hb + o2);
            H3.f = *(const float4*)(hb + o3);
            a0 = fma2(H0.u[0], A0.u, a0); a1 = fma2(H0.u[1], A0.u, a1);
            a0 = fma2(H1.u[0], A1.u, a0); a1 = fma2(H1.u[1], A1.u, a1);
            a0 = fma2(H2.u[0], A2.u, a0); a1 = fma2(H2.u[1], A2.u, a1);
            a0 = fma2(H3.u[0], A3.u, a0); a1 = fma2(H3.u[1], A3.u, a1);
        }
        for (; e < cc; e++) {
            int o = off_sh[g][e];
            F2U A; A.f = al_sh[g][e * H + hd];
            F4U Hv; Hv.f = *(const float4*)(hb + o);
            a0 = fma2(Hv.u[0], A.u, a0);
            a1 = fma2(Hv.u[1], A.u, a1);
        }
        __syncthreads();
    }
    float2 r01 = unpack2(a0), r23 = unpack2(a1);
    float4 b = *(const float4*)&bias[ch0];
    float4 o;
    o.x = fmaxf(r01.x + b.x, 0.f);
    o.y = fmaxf(r01.y + b.y, 0.f);
    o.z = fmaxf(r23.x + b.z, 0.f);
    o.w = fmaxf(r23.y + b.w, 0.f);
    *(float4*)&out[n * HC + ch0] = o;
}

// ---------------- pooling: per-graph reduction (batch is sorted) ----------------
__global__ void pool_kernel(const float* __restrict__ x1, const float* __restrict__ x2,
                            const float* __restrict__ x3, const float* __restrict__ x4,
                            const int* __restrict__ gstart, float* __restrict__ pool) {
    int g = blockIdx.x, q = blockIdx.y, f = threadIdx.x;
    if (f >= 108) return;
    int s = gstart[g], e = gstart[g + 1];
    int len = e - s;
    int n0 = s + len * q / 4;
    int n1 = s + len * (q + 1) / 4;
    const float* src; int stride, off;
    if (f < 4)       { src = x1; stride = 16;  off = 4 * f; }
    else if (f < 12) { src = x2; stride = 32;  off = 4 * (f - 4); }
    else if (f < 44) { src = x3; stride = 128; off = 4 * (f - 12); }
    else             { src = x4; stride = 256; off = 4 * (f - 44); }
    ull a0 = 0ull, a1 = 0ull;
    for (int n = n0; n < n1; n++) {
        F4U v; v.f = *(const float4*)&src[(size_t)n * stride + off];
        a0 = add2(a0, v.u[0]);
        a1 = add2(a1, v.u[1]);
    }
    float2 r01 = unpack2(a0), r23 = unpack2(a1);
    float* dst = &pool[g * 432 + 4 * f];
    atomicAdd(dst + 0, r01.x);
    atomicAdd(dst + 1, r01.y);
    atomicAdd(dst + 2, r23.x);
    atomicAdd(dst + 3, r23.y);
}

// ---------------- final MLP ----------------
__global__ void fc_kernel(const float* __restrict__ pool, const int* __restrict__ gstart,
                          const float* __restrict__ W1, const float* __restrict__ b1,
                          const float* __restrict__ W2, const float* __restrict__ b2,
                          float* __restrict__ out) {
    int g = blockIdx.x, t = threadIdx.x;   // 128 threads
    __shared__ float xp[432];
    __shared__ float ws[4];
    float cntf = (float)(gstart[g + 1] - gstart[g]);
    float invc = 1.f / fmaxf(cntf, 1.f);
    for (int i = t; i < 432; i += 128) xp[i] = pool[g * 432 + i] * invc;
    __syncthreads();
    float acc = b1[t];
    for (int i = 0; i < 432; i++) acc += xp[i] * W1[i * 128 + t];
    acc = fmaxf(acc, 0.f);
    float v = acc * W2[t];
#pragma unroll
    for (int o = 16; o; o >>= 1) v += __shfl_xor_sync(0xffffffffu, v, o);
    if ((t & 31) == 0) ws[t >> 5] = v;
    __syncthreads();
    if (t == 0) out[g] = ws[0] + ws[1] + ws[2] + ws[3] + b2[0];
}

// ---------------- launch ----------------
extern "C" void kernel_launch(void* const* d_in, const int* in_sizes, int n_in,
                              void* d_out, int out_size) {
    const float* x    = (const float*)d_in[0];
    const int*   ei   = (const int*)d_in[1];
    const int*   batch= (const int*)d_in[2];
    const float* W1   = (const float*)d_in[3];
    const float* b1   = (const float*)d_in[4];
    const float* W2   = (const float*)d_in[5];
    const float* b2   = (const float*)d_in[6];
    const float* W3   = (const float*)d_in[7];
    const float* as3  = (const float*)d_in[8];
    const float* ad3  = (const float*)d_in[9];
    const float* b3   = (const float*)d_in[10];
    const float* W4   = (const float*)d_in[11];
    const float* as4  = (const float*)d_in[12];
    const float* ad4  = (const float*)d_in[13];
    const float* b4   = (const float*)d_in[14];
    const float* Wfc1 = (const float*)d_in[15];
    const float* bfc1 = (const float*)d_in[16];
    const float* Wfc2 = (const float*)d_in[17];
    const float* bfc2 = (const float*)d_in[18];
    float* out = (float*)d_out;

    static float *p_x1 = nullptr, *p_x2, *p_x3, *p_x4, *p_h, *p_asrc, *p_adst, *p_m, *p_s,
                 *p_ex, *p_dinv, *p_pool;
    static int *p_counts, *p_rowptr, *p_csr, *p_gstart;
    if (!p_x1) {
        cudaGetSymbolAddress((void**)&p_x1, g_x1);
        cudaGetSymbolAddress((void**)&p_x2, g_x2);
        cudaGetSymbolAddress((void**)&p_x3, g_x3);
        cudaGetSymbolAddress((void**)&p_x4, g_x4);
        cudaGetSymbolAddress((void**)&p_h, g_h);
        cudaGetSymbolAddress((void**)&p_asrc, g_asrc);
        cudaGetSymbolAddress((void**)&p_adst, g_adst);
        cudaGetSymbolAddress((void**)&p_m, g_m);
        cudaGetSymbolAddress((void**)&p_s, g_s);
        cudaGetSymbolAddress((void**)&p_ex, g_ex);
        cudaGetSymbolAddress((void**)&p_dinv, g_dinv);
        cudaGetSymbolAddress((void**)&p_pool, g_pool);
        cudaGetSymbolAddress((void**)&p_counts, g_counts);
        cudaGetSymbolAddress((void**)&p_rowptr, g_rowptr);
        cudaGetSymbolAddress((void**)&p_csr, g_csr_src);
        cudaGetSymbolAddress((void**)&p_gstart, g_gstart);
    }

    // CSR + graph ranges + pool init
    cudaMemsetAsync(p_counts, 0, NN * sizeof(int));
    cudaMemsetAsync(p_pool, 0, GG * 432 * sizeof(float));
    gstart_kernel<<<(NN + 255) / 256, 256>>>(batch, p_gstart);
    count_edges_kernel<<<(ETOT + 255) / 256, 256>>>(ei, p_counts);
    scan_kernel<<<1, 1024>>>(p_counts, p_rowptr);
    prep_kernel<<<(NN + 255) / 256, 256>>>(p_counts, p_rowptr, p_dinv);
    fill_csr_kernel<<<(ETOT + 255) / 256, 256>>>(ei, p_counts, p_csr);

    // GCN layer 1 (128 -> 16)
    {
        dim3 b(4, 16), g((NN + 63) / 64, 1);
        gemm_small_kernel<128, 16><<<g, b>>>(x, W1, p_h);
    }
    gcn_agg_kernel<16><<<(NN * 4 + 255) / 256, 256>>>(p_h, p_dinv, p_rowptr, p_csr, b1, p_x1);

    // GCN layer 2 (16 -> 32)
    {
        dim3 b(8, 16), g((NN + 63) / 64, 1);
        gemm_small_kernel<16, 32><<<g, b>>>(p_x1, W2, p_h);
    }
    gcn_agg_kernel<32><<<(NN * 8 + 255) / 256, 256>>>(p_h, p_dinv, p_rowptr, p_csr, b2, p_x2);

    // GAT layer 3 (32 -> 4x32)
    {
        dim3 b(8, 16), g((NN + 127) / 128, 2);
        gemm_big_kernel<32, 128><<<g, b>>>(p_x2, W3, p_h);
    }
    att_coef_kernel<4><<<(NN * 32 + 255) / 256, 256>>>(p_h, as3, ad3, p_asrc, p_adst);
    gat_maxsum_kernel<4><<<(NN * 32 + 255) / 256, 256>>>(p_asrc, p_adst, p_rowptr, p_csr, p_m, p_s, p_ex);
    gat_agg_kernel<4><<<NN / 4, 128>>>(p_h, p_ex, p_s, p_rowptr, p_csr, b3, p_x3);

    // GAT layer 4 (128 -> 8x32)
    {
        dim3 b(8, 16), g((NN + 127) / 128, 4);
        gemm_big_kernel<128, 256><<<g, b>>>(p_x3, W4, p_h);
    }
    att_coef_kernel<8><<<(NN * 32 + 255) / 256, 256>>>(p_h, as4, ad4, p_asrc, p_adst);
    gat_maxsum_kernel<8><<<(NN * 32 + 255) / 256, 256>>>(p_asrc, p_adst, p_rowptr, p_csr, p_m, p_s, p_ex);
    gat_agg_kernel<8><<<NN / 2, 128>>>(p_h, p_ex, p_s, p_rowptr, p_csr, b4, p_x4);

    // pool + MLP
    {
        dim3 g(GG, 4);
        pool_kernel<<<g, 128>>>(p_x1, p_x2, p_x3, p_x4, p_gstart, p_pool);
    }
    fc_kernel<<<GG, 128>>>(p_pool, p_gstart, Wfc1, bfc1, Wfc2, bfc2, out);
}

// round 3
// speedup vs baseline: 1.5590x; 1.1980x over previous
#include <cuda_runtime.h>

#define NN 50000
#define EE 800000
#define ETOT (EE + NN)
#define GG 128
#define NEG_SLOPE 0.2f
#define RB 49   // ceil(NN/1024)

typedef unsigned long long ull;

union F4U { float4 f; ull u[2]; };
union F2U { float2 f; ull u; };

__device__ __forceinline__ ull fma2(ull a, ull b, ull c) {
    ull d; asm("fma.rn.f32x2 %0,%1,%2,%3;" : "=l"(d) : "l"(a), "l"(b), "l"(c)); return d;
}
__device__ __forceinline__ ull add2(ull a, ull b) {
    ull d; asm("add.rn.f32x2 %0,%1,%2;" : "=l"(d) : "l"(a), "l"(b)); return d;
}
__device__ __forceinline__ ull pack2(float x) {
    F2U t; t.f = make_float2(x, x); return t.u;
}
__device__ __forceinline__ float2 unpack2(ull v) { F2U t; t.u = v; return t.f; }

// ---------------- scratch ----------------
__device__ float g_x1[NN * 16];
__device__ float g_x2[NN * 32];
__device__ float g_x3[NN * 128];
__device__ float g_x4[NN * 256];
__device__ float g_h [NN * 256];
__device__ float g_asrc[NN * 8];
__device__ float g_adst[NN * 8];
__device__ float g_s[NN * 8];
__device__ float g_ex[(size_t)ETOT * 8];
__device__ float g_dinv[NN];
__device__ int   g_counts[NN];
__device__ int   g_bsum[RB];
__device__ int   g_rowptr[NN + 1];
__device__ int   g_csr_src[ETOT];
__device__ int   g_gstart[GG + 1];
__device__ float g_pool[GG * 432];

// ---------------- CSR build ----------------
__global__ void count_edges_kernel(const int* __restrict__ ei, int* __restrict__ counts) {
    int e = blockIdx.x * blockDim.x + threadIdx.x;
    if (e >= ETOT) return;
    int dst = (e < EE) ? ei[EE + e] : (e - EE);
    atomicAdd(&counts[dst], 1);
}

__global__ void scan_reduce_kernel(const int* __restrict__ counts, int* __restrict__ bsum) {
    __shared__ int ws[32];
    int i = blockIdx.x * 1024 + threadIdx.x;
    int v = (i < NN) ? counts[i] : 0;
    int lane = threadIdx.x & 31, w = threadIdx.x >> 5;
#pragma unroll
    for (int o = 16; o; o >>= 1) v += __shfl_xor_sync(0xffffffffu, v, o);
    if (lane == 0) ws[w] = v;
    __syncthreads();
    if (w == 0) {
        int s = ws[lane];
#pragma unroll
        for (int o = 16; o; o >>= 1) s += __shfl_xor_sync(0xffffffffu, s, o);
        if (lane == 0) bsum[blockIdx.x] = s;
    }
}

__global__ void scan_offsets_kernel(int* __restrict__ bsum) {
    __shared__ int ws[2];
    int t = threadIdx.x;   // 64 threads
    int own = (t < RB) ? bsum[t] : 0;
    int v = own;
    int lane = t & 31, w = t >> 5;
#pragma unroll
    for (int o = 1; o < 32; o <<= 1) {
        int u = __shfl_up_sync(0xffffffffu, v, o);
        if (lane >= o) v += u;
    }
    if (lane == 31) ws[w] = v;
    __syncthreads();
    if (w == 1) v += ws[0];
    if (t < RB) bsum[t] = v - own;   // exclusive
}

__global__ void scan_apply_kernel(int* __restrict__ counts, const int* __restrict__ bsum,
                                  int* __restrict__ rowptr, float* __restrict__ dinv) {
    __shared__ int ws[32];
    int i = blockIdx.x * 1024 + threadIdx.x;
    int cnt = (i < NN) ? counts[i] : 0;
    int lane = threadIdx.x & 31, w = threadIdx.x >> 5;
    int v = cnt;
#pragma unroll
    for (int o = 1; o < 32; o <<= 1) {
        int u = __shfl_up_sync(0xffffffffu, v, o);
        if (lane >= o) v += u;
    }
    if (lane == 31) ws[w] = v;
    __syncthreads();
    if (w == 0) {
        int s = ws[lane];
#pragma unroll
        for (int o = 1; o < 32; o <<= 1) {
            int u = __shfl_up_sync(0xffffffffu, s, o);
            if (lane >= o) s += u;
        }
        ws[lane] = s;
    }
    __syncthreads();
    int incl = v + (w ? ws[w - 1] : 0) + bsum[blockIdx.x];
    if (i < NN) {
        rowptr[i + 1] = incl;
        counts[i] = incl - cnt;              // fill cursor
        dinv[i] = rsqrtf((float)(cnt > 0 ? cnt : 1));
    }
    if (i == 0) rowptr[0] = 0;
}

__global__ void fill_csr_kernel(const int* __restrict__ ei, int* __restrict__ cursor,
                                int* __restrict__ csr) {
    int e = blockIdx.x * blockDim.x + threadIdx.x;
    if (e >= ETOT) return;
    int src, dst;
    if (e < EE) { src = ei[e]; dst = ei[EE + e]; }
    else        { src = dst = e - EE; }
    int pos = atomicAdd(&cursor[dst], 1);
    csr[pos] = src;
}

__global__ void gstart_kernel(const int* __restrict__ batch, int* __restrict__ gstart) {
    int n = blockIdx.x * blockDim.x + threadIdx.x;
    if (n >= NN) return;
    int b = batch[n];
    if (n == 0) { for (int g = 0; g <= b; g++) gstart[g] = 0; }
    else {
        int pb = batch[n - 1];
        for (int g = pb + 1; g <= b; g++) gstart[g] = n;
    }
    if (n == NN - 1) { for (int g = b + 1; g <= GG; g++) gstart[g] = NN; }
}

// ---------------- small GEMM (M=16/32) ----------------
template<int K, int M>
__global__ void gemm_small_kernel(const float* __restrict__ X, const float* __restrict__ W,
                                  float* __restrict__ Y) {
    constexpr int CT = M;
    constexpr int KC = (K < 64) ? K : 64;
    constexpr int TX = CT / 4;
    constexpr int NT = TX * 16;
    constexpr int RP = 68;
    __shared__ float Xs[KC * RP];
    __shared__ float Ws[KC * CT];
    int row0 = blockIdx.x * 64;
    int tid = threadIdx.y * TX + threadIdx.x;
    float acc[4][4] = {};
    for (int k0 = 0; k0 < K; k0 += KC) {
        for (int idx = tid; idx < 64 * KC; idx += NT) {
            int r = idx / KC, k = idx % KC;
            int gr = row0 + r;
            Xs[k * RP + r] = (gr < NN) ? X[gr * K + k0 + k] : 0.f;
        }
        for (int idx = tid; idx < KC * CT; idx += NT) {
            int k = idx / CT, c = idx % CT;
            Ws[k * CT + c] = W[(k0 + k) * M + c];
        }
        __syncthreads();
#pragma unroll 8
        for (int k = 0; k < KC; k++) {
            float4 xv = *(const float4*)&Xs[k * RP + 4 * threadIdx.y];
            float4 wv = *(const float4*)&Ws[k * CT + 4 * threadIdx.x];
            float xa[4] = {xv.x, xv.y, xv.z, xv.w};
            float wa[4] = {wv.x, wv.y, wv.z, wv.w};
#pragma unroll
            for (int i = 0; i < 4; i++)
#pragma unroll
                for (int j = 0; j < 4; j++)
                    acc[i][j] += xa[i] * wa[j];
        }
        __syncthreads();
    }
#pragma unroll
    for (int i = 0; i < 4; i++) {
        int r = row0 + 4 * threadIdx.y + i;
        if (r < NN) {
            float4 o = make_float4(acc[i][0], acc[i][1], acc[i][2], acc[i][3]);
            *(float4*)&Y[r * M + 4 * threadIdx.x] = o;
        }
    }
}

// ---------------- big GEMM with optional fused attention-coef epilogue ----------------
template<int K, int M, bool ATT>
__global__ __launch_bounds__(128) void gemm_big_kernel(
        const float* __restrict__ X, const float* __restrict__ W, float* __restrict__ Y,
        const float* __restrict__ att_s, const float* __restrict__ att_d,
        float* __restrict__ asrc, float* __restrict__ adst) {
    constexpr int KC = (K < 32) ? K : 32;
    constexpr int RP = 132;
    constexpr int H = M / 32;
    __shared__ float Xs[KC * RP];
    __shared__ float Ws[KC * 64];
    int tx = threadIdx.x, ty = threadIdx.y;      // (8,16)
    int tid = ty * 8 + tx;
    int row0 = blockIdx.x * 128;
    int c0 = blockIdx.y * 64;
    ull acc[4][8];
#pragma unroll
    for (int p = 0; p < 4; p++)
#pragma unroll
        for (int j = 0; j < 8; j++) acc[p][j] = 0ull;

    for (int k0 = 0; k0 < K; k0 += KC) {
        for (int idx = tid; idx < 128 * (KC / 4); idx += 128) {
            int r = idx / (KC / 4);
            int k4 = (idx % (KC / 4)) * 4;
            int gr = row0 + r;
            float4 v = make_float4(0.f, 0.f, 0.f, 0.f);
            if (gr < NN) v = *(const float4*)&X[gr * K + k0 + k4];
            Xs[(k4 + 0) * RP + r] = v.x;
            Xs[(k4 + 1) * RP + r] = v.y;
            Xs[(k4 + 2) * RP + r] = v.z;
            Xs[(k4 + 3) * RP + r] = v.w;
        }
        for (int idx = tid; idx < KC * 16; idx += 128) {
            int k = idx / 16;
            int c4 = (idx % 16) * 4;
            *(float4*)&Ws[k * 64 + c4] = *(const float4*)&W[(k0 + k) * M + c0 + c4];
        }
        __syncthreads();
#pragma unroll 8
        for (int k = 0; k < KC; k++) {
            const float* xr = &Xs[k * RP + 8 * ty];
            F4U xa, xb;
            xa.f = *(const float4*)xr;
            xb.f = *(const float4*)(xr + 4);
            ull x2[4] = {xa.u[0], xa.u[1], xb.u[0], xb.u[1]};
            const float* wr = &Ws[k * 64 + 8 * tx];
            float4 wa = *(const float4*)wr;
            float4 wb = *(const float4*)(wr + 4);
            ull w2[8];
            w2[0] = pack2(wa.x); w2[1] = pack2(wa.y); w2[2] = pack2(wa.z); w2[3] = pack2(wa.w);
            w2[4] = pack2(wb.x); w2[5] = pack2(wb.y); w2[6] = pack2(wb.z); w2[7] = pack2(wb.w);
#pragma unroll
            for (int p = 0; p < 4; p++)
#pragma unroll
                for (int j = 0; j < 8; j++)
                    acc[p][j] = fma2(x2[p], w2[j], acc[p][j]);
        }
        __syncthreads();
    }
    // store Y
#pragma unroll
    for (int p = 0; p < 4; p++) {
        float rlo[8], rhi[8];
#pragma unroll
        for (int j = 0; j < 8; j++) {
            float2 t = unpack2(acc[p][j]);
            rlo[j] = t.x; rhi[j] = t.y;
        }
        int r = row0 + 8 * ty + 2 * p;
        if (r < NN) {
            *(float4*)&Y[r * M + c0 + 8 * tx]     = make_float4(rlo[0], rlo[1], rlo[2], rlo[3]);
            *(float4*)&Y[r * M + c0 + 8 * tx + 4] = make_float4(rlo[4], rlo[5], rlo[6], rlo[7]);
        }
        if (r + 1 < NN) {
            *(float4*)&Y[(r + 1) * M + c0 + 8 * tx]     = make_float4(rhi[0], rhi[1], rhi[2], rhi[3]);
            *(float4*)&Y[(r + 1) * M + c0 + 8 * tx + 4] = make_float4(rhi[4], rhi[5], rhi[6], rhi[7]);
        }
    }
    // fused attention coefficients: tile covers 2 complete heads
    if constexpr (ATT) {
        int head = (c0 >> 5) + (tx >> 2);
        int cbase = (8 * tx) & 31;
        ull asv[8], adv[8];
#pragma unroll
        for (int j = 0; j < 8; j++) {
            asv[j] = pack2(att_s[head * 32 + cbase + j]);
            adv[j] = pack2(att_d[head * 32 + cbase + j]);
        }
#pragma unroll
        for (int p = 0; p < 4; p++) {
            ull s2 = 0ull, d2 = 0ull;
#pragma unroll
            for (int j = 0; j < 8; j++) {
                s2 = fma2(acc[p][j], asv[j], s2);
                d2 = fma2(acc[p][j], adv[j], d2);
            }
            // reduce over 4 consecutive lanes (tx groups aligned to 4)
            s2 = add2(s2, __shfl_xor_sync(0xffffffffu, s2, 1));
            s2 = add2(s2, __shfl_xor_sync(0xffffffffu, s2, 2));
            d2 = add2(d2, __shfl_xor_sync(0xffffffffu, d2, 1));
            d2 = add2(d2, __shfl_xor_sync(0xffffffffu, d2, 2));
            if ((tx & 3) == 0) {
                float2 sv = unpack2(s2), dv = unpack2(d2);
                int r = row0 + 8 * ty + 2 * p;
                if (r < NN)     { asrc[r * H + head] = sv.x; adst[r * H + head] = dv.x; }
                if (r + 1 < NN) { asrc[(r + 1) * H + head] = sv.y; adst[(r + 1) * H + head] = dv.y; }
            }
        }
    }
}

// ---------------- GCN aggregate ----------------
template<int C>
__global__ void gcn_agg_kernel(const float* __restrict__ h, const float* __restrict__ dinv,
                               const int* __restrict__ rowptr, const int* __restrict__ csr,
                               const float* __restrict__ bias, float* __restrict__ out) {
    constexpr int TPN = C / 4;
    int gtid = blockIdx.x * blockDim.x + threadIdx.x;
    int n = gtid / TPN;
    int ch = 4 * (gtid % TPN);
    if (n >= NN) return;
    int r0 = rowptr[n], r1 = rowptr[n + 1];
    const float* hb = h + ch;
    ull a0 = 0ull, a1 = 0ull;
    for (int j = r0; j < r1; j++) {
        int s = csr[j];
        ull dv2 = pack2(dinv[s]);
        F4U hv; hv.f = *(const float4*)(hb + s * C);
        a0 = fma2(hv.u[0], dv2, a0);
        a1 = fma2(hv.u[1], dv2, a1);
    }
    float dn = dinv[n];
    float2 r01 = unpack2(a0), r23 = unpack2(a1);
    float4 b = *(const float4*)&bias[ch];
    float4 o;
    o.x = fmaxf(r01.x * dn + b.x, 0.f);
    o.y = fmaxf(r01.y * dn + b.y, 0.f);
    o.z = fmaxf(r23.x * dn + b.z, 0.f);
    o.w = fmaxf(r23.y * dn + b.w, 0.f);
    *(float4*)&out[n * C + ch] = o;
}

// ---------------- GAT: max + sum(exp), cache exp(e-m) ----------------
template<int H>
__global__ void gat_maxsum_kernel(const float* __restrict__ asrc, const float* __restrict__ adst,
                                  const int* __restrict__ rowptr, const int* __restrict__ csr,
                                  float* __restrict__ sArr, float* __restrict__ ex) {
    int warp = (blockIdx.x * blockDim.x + threadIdx.x) >> 5;
    int lane = threadIdx.x & 31;
    int n = warp;
    if (n >= NN) return;
    float ad[H];
#pragma unroll
    for (int q = 0; q < H / 4; q++) {
        float4 v = *(const float4*)&adst[n * H + 4 * q];
        ad[4 * q + 0] = v.x; ad[4 * q + 1] = v.y; ad[4 * q + 2] = v.z; ad[4 * q + 3] = v.w;
    }
    int r0 = rowptr[n], r1 = rowptr[n + 1];
    float mx[H];
#pragma unroll
    for (int hd = 0; hd < H; hd++) mx[hd] = -1e30f;
    for (int j = r0 + lane; j < r1; j += 32) {
        int s = csr[j];
        float as[H];
#pragma unroll
        for (int q = 0; q < H / 4; q++) {
            float4 v = *(const float4*)&asrc[s * H + 4 * q];
            as[4 * q + 0] = v.x; as[4 * q + 1] = v.y; as[4 * q + 2] = v.z; as[4 * q + 3] = v.w;
        }
#pragma unroll
        for (int hd = 0; hd < H; hd++) {
            float e = as[hd] + ad[hd];
            e = fmaxf(e, NEG_SLOPE * e);
            mx[hd] = fmaxf(mx[hd], e);
        }
    }
#pragma unroll
    for (int hd = 0; hd < H; hd++)
#pragma unroll
        for (int o = 16; o; o >>= 1) mx[hd] = fmaxf(mx[hd], __shfl_xor_sync(0xffffffffu, mx[hd], o));
    float sm[H];
#pragma unroll
    for (int hd = 0; hd < H; hd++) sm[hd] = 0.f;
    for (int j = r0 + lane; j < r1; j += 32) {
        int s = csr[j];
        float as[H];
#pragma unroll
        for (int q = 0; q < H / 4; q++) {
            float4 v = *(const float4*)&asrc[s * H + 4 * q];
            as[4 * q + 0] = v.x; as[4 * q + 1] = v.y; as[4 * q + 2] = v.z; as[4 * q + 3] = v.w;
        }
        float exv[H];
#pragma unroll
        for (int hd = 0; hd < H; hd++) {
            float e = as[hd] + ad[hd];
            e = fmaxf(e, NEG_SLOPE * e);
            float xv = __expf(e - mx[hd]);
            exv[hd] = xv;
            sm[hd] += xv;
        }
#pragma unroll
        for (int q = 0; q < H / 4; q++)
            *(float4*)&ex[(size_t)j * H + 4 * q] =
                make_float4(exv[4 * q + 0], exv[4 * q + 1], exv[4 * q + 2], exv[4 * q + 3]);
    }
#pragma unroll
    for (int hd = 0; hd < H; hd++)
#pragma unroll
        for (int o = 16; o; o >>= 1) sm[hd] += __shfl_xor_sync(0xffffffffu, sm[hd], o);
    if (lane == 0) {
#pragma unroll
        for (int hd = 0; hd < H; hd++) sArr[n * H + hd] = sm[hd];
    }
}

// ---------------- GAT aggregation ----------------
template<int H>
__global__ __launch_bounds__(128) void gat_agg_kernel(
        const float* __restrict__ h, const float* __restrict__ ex,
        const float* __restrict__ sArr, const int* __restrict__ rowptr,
        const int* __restrict__ csr, const float* __restrict__ bias,
        float* __restrict__ out) {
    constexpr int HC = H * 32;
    constexpr int TPN = HC / 4;
    constexpr int NPB = 128 / TPN;
    constexpr int CH = 32;
    __shared__ float2 al_sh[NPB][CH * H];
    __shared__ int off_sh[NPB][CH];
    __shared__ float inv_sh[NPB][H];
    __shared__ int r0_sh[NPB];
    __shared__ int cnt_sh[NPB];
    __shared__ int mx_sh;

    int tid = threadIdx.x;
    int g = tid / TPN, tg = tid % TPN;
    int n = blockIdx.x * NPB + g;
    if (tid == 0) mx_sh = 0;
    if (tg < H) inv_sh[g][tg] = 1.f / sArr[n * H + tg];
    if (tg == 0) {
        int r0 = rowptr[n], r1 = rowptr[n + 1];
        r0_sh[g] = r0;
        cnt_sh[g] = r1 - r0;
    }
    __syncthreads();
    if (tg == 0) atomicMax(&mx_sh, cnt_sh[g]);
    __syncthreads();
    int cnt = cnt_sh[g], r0 = r0_sh[g];
    int nch = (mx_sh + CH - 1) / CH;
    int ch0 = 4 * tg;
    int hd = tg >> 3;
    const float* hb = h + ch0;
    ull a0 = 0ull, a1 = 0ull;

    for (int c = 0; c < nch; c++) {
        int base = c * CH;
        int cc = min(CH, cnt - base);
#pragma unroll
        for (int it = 0; it < CH * H / TPN; it++) {
            int task = tg + it * TPN;
            int e = task / H;
            int hh = task - e * H;
            if (e < cc) {
                int j = r0 + base + e;
                float a = ex[(size_t)j * H + hh] * inv_sh[g][hh];
                al_sh[g][task] = make_float2(a, a);
                if (hh == 0) off_sh[g][e] = csr[j] * HC;
            }
        }
        __syncthreads();
        int e = 0;
        for (; e + 4 <= cc; e += 4) {
            int o0 = off_sh[g][e], o1 = off_sh[g][e + 1], o2 = off_sh[g][e + 2], o3 = off_sh[g][e + 3];
            F2U A0, A1, A2, A3;
            A0.f = al_sh[g][(e + 0) * H + hd];
            A1.f = al_sh[g][(e + 1) * H + hd];
            A2.f = al_sh[g][(e + 2) * H + hd];
            A3.f = al_sh[g][(e + 3) * H + hd];
            F4U H0, H1, H2, H3;
            H0.f = *(const float4*)(hb + o0);
            H1.f = *(const float4*)(hb + o1);
            H2.f = *(const float4*)(hb + o2);
            H3.f = *(const float4*)(hb + o3);
            a0 = fma2(H0.u[0], A0.u, a0); a1 = fma2(H0.u[1], A0.u, a1);
            a0 = fma2(H1.u[0], A1.u, a0); a1 = fma2(H1.u[1], A1.u, a1);
            a0 = fma2(H2.u[0], A2.u, a0); a1 = fma2(H2.u[1], A2.u, a1);
            a0 = fma2(H3.u[0], A3.u, a0); a1 = fma2(H3.u[1], A3.u, a1);
        }
        for (; e < cc; e++) {
            int o = off_sh[g][e];
            F2U A; A.f = al_sh[g][e * H + hd];
            F4U Hv; Hv.f = *(const float4*)(hb + o);
            a0 = fma2(Hv.u[0], A.u, a0);
            a1 = fma2(Hv.u[1], A.u, a1);
        }
        __syncthreads();
    }
    float2 r01 = unpack2(a0), r23 = unpack2(a1);
    float4 b = *(const float4*)&bias[ch0];
    float4 o;
    o.x = fmaxf(r01.x + b.x, 0.f);
    o.y = fmaxf(r01.y + b.y, 0.f);
    o.z = fmaxf(r23.x + b.z, 0.f);
    o.w = fmaxf(r23.y + b.w, 0.f);
    *(float4*)&out[n * HC + ch0] = o;
}

// ---------------- pooling partials per layer ----------------
template<int NF4>
__global__ void pool_part_kernel(const float* __restrict__ src, int obase, int qy_total,
                                 const int* __restrict__ gstart, float* __restrict__ pool) {
    constexpr int SPB = 128 / NF4;
    int g = blockIdx.x;
    int q = blockIdx.y * SPB + threadIdx.x / NF4;
    int f = threadIdx.x % NF4;
    int slices = qy_total * SPB;
    int s = gstart[g], e = gstart[g + 1];
    int len = e - s;
    int n0 = s + (int)((long long)len * q / slices);
    int n1 = s + (int)((long long)len * (q + 1) / slices);
    ull a0 = 0ull, a1 = 0ull;
    int stride = NF4 * 4;
    for (int n = n0; n < n1; n++) {
        F4U v; v.f = *(const float4*)&src[(size_t)n * stride + 4 * f];
        a0 = add2(a0, v.u[0]);
        a1 = add2(a1, v.u[1]);
    }
    float2 r01 = unpack2(a0), r23 = unpack2(a1);
    float* dst = &pool[g * 432 + obase + 4 * f];
    atomicAdd(dst + 0, r01.x);
    atomicAdd(dst + 1, r01.y);
    atomicAdd(dst + 2, r23.x);
    atomicAdd(dst + 3, r23.y);
}

// ---------------- final MLP ----------------
__global__ void fc_kernel(const float* __restrict__ pool, const int* __restrict__ gstart,
                          const float* __restrict__ W1, const float* __restrict__ b1,
                          const float* __restrict__ W2, const float* __restrict__ b2,
                          float* __restrict__ out) {
    int g = blockIdx.x, t = threadIdx.x;
    __shared__ float xp[432];
    __shared__ float ws[4];
    float cntf = (float)(gstart[g + 1] - gstart[g]);
    float invc = 1.f / fmaxf(cntf, 1.f);
    for (int i = t; i < 432; i += 128) xp[i] = pool[g * 432 + i] * invc;
    __syncthreads();
    float acc = b1[t];
    for (int i = 0; i < 432; i++) acc += xp[i] * W1[i * 128 + t];
    acc = fmaxf(acc, 0.f);
    float v = acc * W2[t];
#pragma unroll
    for (int o = 16; o; o >>= 1) v += __shfl_xor_sync(0xffffffffu, v, o);
    if ((t & 31) == 0) ws[t >> 5] = v;
    __syncthreads();
    if (t == 0) out[g] = ws[0] + ws[1] + ws[2] + ws[3] + b2[0];
}

// ---------------- launch ----------------
extern "C" void kernel_launch(void* const* d_in, const int* in_sizes, int n_in,
                              void* d_out, int out_size) {
    const float* x    = (const float*)d_in[0];
    const int*   ei   = (const int*)d_in[1];
    const int*   batch= (const int*)d_in[2];
    const float* W1   = (const float*)d_in[3];
    const float* b1   = (const float*)d_in[4];
    const float* W2   = (const float*)d_in[5];
    const float* b2   = (const float*)d_in[6];
    const float* W3   = (const float*)d_in[7];
    const float* as3  = (const float*)d_in[8];
    const float* ad3  = (const float*)d_in[9];
    const float* b3   = (const float*)d_in[10];
    const float* W4   = (const float*)d_in[11];
    const float* as4  = (const float*)d_in[12];
    const float* ad4  = (const float*)d_in[13];
    const float* b4   = (const float*)d_in[14];
    const float* Wfc1 = (const float*)d_in[15];
    const float* bfc1 = (const float*)d_in[16];
    const float* Wfc2 = (const float*)d_in[17];
    const float* bfc2 = (const float*)d_in[18];
    float* out = (float*)d_out;

    static float *p_x1 = nullptr, *p_x2, *p_x3, *p_x4, *p_h, *p_asrc, *p_adst, *p_s,
                 *p_ex, *p_dinv, *p_pool;
    static int *p_counts, *p_bsum, *p_rowptr, *p_csr, *p_gstart;
    static cudaStream_t s1, s2;
    static cudaEvent_t evRoot, evG1, evX1, evX2, evX3, evX4, evFC;
    if (!p_x1) {
        cudaGetSymbolAddress((void**)&p_x1, g_x1);
        cudaGetSymbolAddress((void**)&p_x2, g_x2);
        cudaGetSymbolAddress((void**)&p_x3, g_x3);
        cudaGetSymbolAddress((void**)&p_x4, g_x4);
        cudaGetSymbolAddress((void**)&p_h, g_h);
        cudaGetSymbolAddress((void**)&p_asrc, g_asrc);
        cudaGetSymbolAddress((void**)&p_adst, g_adst);
        cudaGetSymbolAddress((void**)&p_s, g_s);
        cudaGetSymbolAddress((void**)&p_ex, g_ex);
        cudaGetSymbolAddress((void**)&p_dinv, g_dinv);
        cudaGetSymbolAddress((void**)&p_pool, g_pool);
        cudaGetSymbolAddress((void**)&p_counts, g_counts);
        cudaGetSymbolAddress((void**)&p_bsum, g_bsum);
        cudaGetSymbolAddress((void**)&p_rowptr, g_rowptr);
        cudaGetSymbolAddress((void**)&p_csr, g_csr_src);
        cudaGetSymbolAddress((void**)&p_gstart, g_gstart);
        cudaStreamCreateWithFlags(&s1, cudaStreamNonBlocking);
        cudaStreamCreateWithFlags(&s2, cudaStreamNonBlocking);
        cudaEventCreateWithFlags(&evRoot, cudaEventDisableTiming);
        cudaEventCreateWithFlags(&evG1, cudaEventDisableTiming);
        cudaEventCreateWithFlags(&evX1, cudaEventDisableTiming);
        cudaEventCreateWithFlags(&evX2, cudaEventDisableTiming);
        cudaEventCreateWithFlags(&evX3, cudaEventDisableTiming);
        cudaEventCreateWithFlags(&evX4, cudaEventDisableTiming);
        cudaEventCreateWithFlags(&evFC, cudaEventDisableTiming);
    }

    // fork
    cudaEventRecord(evRoot, 0);
    cudaStreamWaitEvent(s1, evRoot, 0);
    cudaStreamWaitEvent(s2, evRoot, 0);

    // s0: CSR chain
    cudaMemsetAsync(p_counts, 0, NN * sizeof(int), 0);
    count_edges_kernel<<<(ETOT + 255) / 256, 256>>>(ei, p_counts);
    scan_reduce_kernel<<<RB, 1024>>>(p_counts, p_bsum);
    scan_offsets_kernel<<<1, 64>>>(p_bsum);
    scan_apply_kernel<<<RB, 1024>>>(p_counts, p_bsum, p_rowptr, p_dinv);
    fill_csr_kernel<<<(ETOT + 255) / 256, 256>>>(ei, p_counts, p_csr);

    // s1: gstart + pool init (independent)
    gstart_kernel<<<(NN + 255) / 256, 256, 0, s1>>>(batch, p_gstart);
    cudaMemsetAsync(p_pool, 0, GG * 432 * sizeof(float), s1);

    // s2: GEMM1 (independent of CSR)
    {
        dim3 b(4, 16), g((NN + 63) / 64, 1);
        gemm_small_kernel<128, 16><<<g, b, 0, s2>>>(x, W1, p_h);
        cudaEventRecord(evG1, s2);
    }

    // GCN layer 1 aggregate (needs CSR + GEMM1)
    cudaStreamWaitEvent(0, evG1, 0);
    gcn_agg_kernel<16><<<(NN * 4 + 255) / 256, 256>>>(p_h, p_dinv, p_rowptr, p_csr, b1, p_x1);
    cudaEventRecord(evX1, 0);
    cudaStreamWaitEvent(s1, evX1, 0);
    pool_part_kernel<4><<<dim3(GG, 1), 128, 0, s1>>>(p_x1, 0, 1, p_gstart, p_pool);

    // GCN layer 2
    {
        dim3 b(8, 16), g((NN + 63) / 64, 1);
        gemm_small_kernel<16, 32><<<g, b>>>(p_x1, W2, p_h);
    }
    gcn_agg_kernel<32><<<(NN * 8 + 255) / 256, 256>>>(p_h, p_dinv, p_rowptr, p_csr, b2, p_x2);
    cudaEventRecord(evX2, 0);
    cudaStreamWaitEvent(s1, evX2, 0);
    pool_part_kernel<8><<<dim3(GG, 1), 128, 0, s1>>>(p_x2, 16, 1, p_gstart, p_pool);

    // GAT layer 3 (32 -> 4x32), att fused in GEMM
    {
        dim3 b(8, 16), g((NN + 127) / 128, 2);
        gemm_big_kernel<32, 128, true><<<g, b>>>(p_x2, W3, p_h, as3, ad3, p_asrc, p_adst);
    }
    gat_maxsum_kernel<4><<<(NN * 32 + 255) / 256, 256>>>(p_asrc, p_adst, p_rowptr, p_csr, p_s, p_ex);
    gat_agg_kernel<4><<<NN / 4, 128>>>(p_h, p_ex, p_s, p_rowptr, p_csr, b3, p_x3);
    cudaEventRecord(evX3, 0);
    cudaStreamWaitEvent(s1, evX3, 0);
    pool_part_kernel<32><<<dim3(GG, 2), 128, 0, s1>>>(p_x3, 48, 2, p_gstart, p_pool);

    // GAT layer 4 (128 -> 8x32), att fused in GEMM
    {
        dim3 b(8, 16), g((NN + 127) / 128, 4);
        gemm_big_kernel<128, 256, true><<<g, b>>>(p_x3, W4, p_h, as4, ad4, p_asrc, p_adst);
    }
    gat_maxsum_kernel<8><<<(NN * 32 + 255) / 256, 256>>>(p_asrc, p_adst, p_rowptr, p_csr, p_s, p_ex);
    gat_agg_kernel<8><<<NN / 2, 128>>>(p_h, p_ex, p_s, p_rowptr, p_csr, b4, p_x4);
    cudaEventRecord(evX4, 0);
    cudaStreamWaitEvent(s1, evX4, 0);
    pool_part_kernel<64><<<dim3(GG, 4), 128, 0, s1>>>(p_x4, 176, 4, p_gstart, p_pool);

    // FC on s1 (all pools + gstart live there)
    fc_kernel<<<GG, 128, 0, s1>>>(p_pool, p_gstart, Wfc1, bfc1, Wfc2, bfc2, out);
    cudaEventRecord(evFC, s1);
    cudaStreamWaitEvent(0, evFC, 0);
}